// round 5
// baseline (speedup 1.0000x reference)
#include <cuda_runtime.h>
#include <cuda_fp16.h>
#include <cstdint>
#include <cstddef>

#define TOK  4096
#define DDIM 1024
#define WDIM 4096

// ------------------------- device scratch (no allocs) -------------------------
__device__ float g_slots[TOK * 8];                  // [tok][slot]
__device__ float g_weff[72 * WDIM];                 // [(l*9+c)][w]
__device__ __half g_ahi[(size_t)TOK * WDIM];        // roots hi  [tok][k=w]
__device__ __half g_alo[(size_t)TOK * WDIM];        // roots lo
__device__ __half g_bhi[(size_t)DDIM * WDIM];       // out_w^T hi [n=d][k=w]
__device__ __half g_blo[(size_t)DDIM * WDIM];       // out_w^T lo

// ------------------------------- helpers --------------------------------------
__device__ __forceinline__ float fast_tanh(float x) {
    float e = __expf(2.0f * x);
    return 1.0f - __fdividef(2.0f, e + 1.0f);
}

__device__ __forceinline__ uint32_t smem_u32(const void* p) {
    uint32_t a;
    asm("{ .reg .u64 t; cvta.to.shared.u64 t, %1; cvt.u32.u64 %0, t; }" : "=r"(a) : "l"(p));
    return a;
}

#define CP16(dst, src) \
    asm volatile("cp.async.cg.shared.global [%0], [%1], 16;" :: "r"(dst), "l"(src) : "memory")
#define CP_COMMIT() asm volatile("cp.async.commit_group;" ::: "memory")
#define CP_WAIT0()  asm volatile("cp.async.wait_group 0;" ::: "memory")
#define CP_WAIT1()  asm volatile("cp.async.wait_group 1;" ::: "memory")

__device__ __forceinline__ void ldsm4(uint32_t (&r)[4], uint32_t addr) {
    asm volatile("ldmatrix.sync.aligned.m8n8.x4.shared.b16 {%0,%1,%2,%3}, [%4];"
                 : "=r"(r[0]), "=r"(r[1]), "=r"(r[2]), "=r"(r[3]) : "r"(addr));
}

__device__ __forceinline__ void mma16816(float (&d)[4], const uint32_t (&a)[4],
                                         uint32_t b0, uint32_t b1) {
    asm volatile("mma.sync.aligned.m16n8k16.row.col.f32.f16.f16.f32 "
                 "{%0,%1,%2,%3}, {%4,%5,%6,%7}, {%8,%9}, {%0,%1,%2,%3};"
                 : "+f"(d[0]), "+f"(d[1]), "+f"(d[2]), "+f"(d[3])
                 : "r"(a[0]), "r"(a[1]), "r"(a[2]), "r"(a[3]), "r"(b0), "r"(b1));
}

// SW128 swizzle for 128B rows (64 fp16 per row)
__device__ __forceinline__ uint32_t swz(uint32_t row, uint32_t bytecol) {
    return row * 128u + (bytecol ^ ((row & 7u) << 4));
}

// -------------------- kernel 1: softmax -> effective leaf weights --------------
__global__ void __launch_bounds__(256) weff_kernel(const float* __restrict__ logits) {
    const int idx = blockIdx.x * 256 + threadIdx.x;   // (w,l)
    if (idx >= WDIM * 8) return;
    const int w = idx >> 3, l = idx & 7;
    const float* p = logits + (size_t)idx * 11;
    float x[11], m = -1e30f;
#pragma unroll
    for (int c = 0; c < 11; c++) { x[c] = p[c]; m = fmaxf(m, x[c]); }
    float s = 0.f;
#pragma unroll
    for (int c = 0; c < 11; c++) { x[c] = __expf(x[c] - m); s += x[c]; }
    const float inv = 1.0f / s;
#pragma unroll
    for (int c = 0; c < 8; c++) g_weff[(l * 9 + c) * WDIM + w] = x[c] * inv;
    g_weff[(l * 9 + 8) * WDIM + w] = (x[10] - x[8]) * inv;   // -1*sel8 + 0*sel9 + 1*sel10
}

// ------------- kernel 2: out_w transpose + fp16 hi/lo split  [d][w] ------------
__global__ void __launch_bounds__(256) split_b_kernel(const float* __restrict__ ow) {
    __shared__ float tile[32][33];
    const int kt = blockIdx.x * 32, nt = blockIdx.y * 32;
    const int tx = threadIdx.x, ty = threadIdx.y;   // (32,8)
#pragma unroll
    for (int i = 0; i < 32; i += 8)
        tile[ty + i][tx] = ow[(size_t)(kt + ty + i) * DDIM + nt + tx];
    __syncthreads();
#pragma unroll
    for (int i = 0; i < 32; i += 8) {
        const int n = nt + ty + i, k = kt + tx;
        const float v = tile[tx][ty + i];
        const __half hi = __float2half_rn(v);
        g_bhi[(size_t)n * WDIM + k] = hi;
        g_blo[(size_t)n * WDIM + k] = __float2half_rn(v - __half2float(hi));
    }
}

// -------------- kernel 3: slots = tanh(hidden @ slot_w + slot_b) ---------------
__global__ void __launch_bounds__(256) slots_kernel(const float* __restrict__ hidden,
                                                    const float* __restrict__ slot_w,
                                                    const float* __restrict__ slot_b) {
    __shared__ float sred[64];
    const int tok = blockIdx.x;
    const int tid = threadIdx.x, lane = tid & 31, warp = tid >> 5;
    float acc[8];
#pragma unroll
    for (int s = 0; s < 8; s++) acc[s] = 0.f;
    const float4* h4 = reinterpret_cast<const float4*>(hidden + (size_t)tok * DDIM);
    for (int i = tid; i < DDIM / 4; i += 256) {
        const float4 h = h4[i];
        const int d = i * 4;
#pragma unroll
        for (int j = 0; j < 4; j++) {
            const float hv = (j == 0) ? h.x : (j == 1) ? h.y : (j == 2) ? h.z : h.w;
            const float4* w4 = reinterpret_cast<const float4*>(slot_w + (size_t)(d + j) * 8);
            const float4 wa = w4[0], wb = w4[1];
            acc[0] = fmaf(hv, wa.x, acc[0]); acc[1] = fmaf(hv, wa.y, acc[1]);
            acc[2] = fmaf(hv, wa.z, acc[2]); acc[3] = fmaf(hv, wa.w, acc[3]);
            acc[4] = fmaf(hv, wb.x, acc[4]); acc[5] = fmaf(hv, wb.y, acc[5]);
            acc[6] = fmaf(hv, wb.z, acc[6]); acc[7] = fmaf(hv, wb.w, acc[7]);
        }
    }
#pragma unroll
    for (int s = 0; s < 8; s++)
#pragma unroll
        for (int o = 16; o > 0; o >>= 1)
            acc[s] += __shfl_xor_sync(0xffffffffu, acc[s], o);
    if (lane == 0) {
#pragma unroll
        for (int s = 0; s < 8; s++) sred[warp * 8 + s] = acc[s];
    }
    __syncthreads();
    if (tid < 8) {
        float v = slot_b[tid];
#pragma unroll
        for (int wp = 0; wp < 8; wp++) v += sred[wp * 8 + tid];
        g_slots[(size_t)tok * 8 + tid] = fast_tanh(v);
    }
}

// ---------------- kernel 4: roots via 3-level tree over 8 leaves ---------------
// grid (WDIM/256, TOK/128), 256 threads; thread owns one w, iterates 128 tokens.
__global__ void __launch_bounds__(256) roots_kernel(const float* __restrict__ np) {
    __shared__ float ssl[128 * 8];
    const int tid = threadIdx.x;
    const int w = blockIdx.x * 256 + tid;
    const int t0 = blockIdx.y * 128;

    float wt[72];
#pragma unroll
    for (int i = 0; i < 72; i++) wt[i] = g_weff[i * WDIM + w];

    {
        const float4* src = reinterpret_cast<const float4*>(g_slots + (size_t)t0 * 8);
        reinterpret_cast<float4*>(ssl)[tid] = src[tid];
    }
    // fold: lw*L + rw*R + pw*L*R + dw*(L-R) + nb = (lw+dw)*L + (rw-dw)*R + pw*L*R + nb
    const float lwp = np[0] + np[3], rwm = np[1] - np[3], pw = np[2], nb = np[4];
    __syncthreads();

#pragma unroll 1
    for (int t = 0; t < 128; t++) {
        float s[8];
#pragma unroll
        for (int c = 0; c < 8; c++) s[c] = ssl[t * 8 + c];
        float v[8];
#pragma unroll
        for (int l = 0; l < 8; l++) {
            float a = wt[l * 9 + 8];
#pragma unroll
            for (int c = 0; c < 8; c++) a = fmaf(wt[l * 9 + c], s[c], a);
            v[l] = a;
        }
#pragma unroll
        for (int lvl = 0; lvl < 3; lvl++) {
            const int n = 8 >> (lvl + 1);
#pragma unroll
            for (int i = 0; i < 4; i++) {
                if (i < n) {
                    const float L = v[2 * i], R = v[2 * i + 1];
                    float a = fmaf(lwp, L, nb);
                    a = fmaf(rwm, R, a);
                    a = fmaf(pw * L, R, a);
                    v[i] = fast_tanh(a);
                }
            }
        }
        const float root = v[0];
        const __half hi = __float2half_rn(root);
        const size_t o = (size_t)(t0 + t) * WDIM + w;
        g_ahi[o] = hi;
        g_alo[o] = __float2half_rn(root - __half2float(hi));
    }
}

// ------------------- kernel 5: out = roots @ out_w + out_b ---------------------
// mma.sync fp16 3-split. CTA tile 128(M)x256(N), K-chunk 64, 2-stage cp.async.
// 512 threads = 16 warps in 4x4 grid; warp tile 32(M)x64(N).
#define STG      98304                      // bytes per stage
#define A_HI_OFF 0                          // 128 x 64 fp16 = 16KB
#define A_LO_OFF 16384
#define B_HI_OFF 32768                      // 256 x 64 fp16 = 32KB
#define B_LO_OFF 65536
#define GEMM_SMEM (2 * STG + 1024)

__device__ __forceinline__ void load_tile(const __half* __restrict__ g, int rows,
                                          uint32_t sb, int tid) {
    // rows x 64 halves (128B rows), swizzled, 16B granules, 512 threads
    const int n16 = rows * 8;
    for (int e = tid; e < n16; e += 512) {
        const int r = e >> 3, c = e & 7;
        CP16(sb + swz((uint32_t)r, (uint32_t)(c * 16)), g + (size_t)r * WDIM + c * 8);
    }
}

__global__ void __launch_bounds__(512, 1) gemm_kernel(float* __restrict__ out,
                                                      const float* __restrict__ out_b) {
    extern __shared__ char dsm[];
    const uint32_t tb = (smem_u32(dsm) + 1023u) & ~1023u;

    const int tid = threadIdx.x, lane = tid & 31, wid = tid >> 5;
    const int mt = blockIdx.x & 31, nt = blockIdx.x >> 5;
    const int wm = wid & 3, wn = wid >> 2;         // 4x4 warp grid

    const __half* Ah = g_ahi + (size_t)(mt * 128) * WDIM;
    const __half* Al = g_alo + (size_t)(mt * 128) * WDIM;
    const __half* Bh = g_bhi + (size_t)(nt * 256) * WDIM;
    const __half* Bl = g_blo + (size_t)(nt * 256) * WDIM;

    float d[2][8][4];
#pragma unroll
    for (int t = 0; t < 2; t++)
#pragma unroll
        for (int j = 0; j < 8; j++)
#pragma unroll
            for (int q = 0; q < 4; q++) d[t][j][q] = 0.f;

    // ldmatrix lane addressing (within a 16x16 b16 tile, 128B rows)
    const uint32_t a_row = (uint32_t)(lane & 15);
    const uint32_t a_bc  = (uint32_t)((lane >> 4) * 16);
    const uint32_t b_row = (uint32_t)(((lane >> 4) << 3) + (lane & 7));
    const uint32_t b_bc  = (uint32_t)(((lane >> 3) & 1) * 16);

    // prologue
    load_tile(Ah, 128, tb + A_HI_OFF, tid);
    load_tile(Al, 128, tb + A_LO_OFF, tid);
    load_tile(Bh, 256, tb + B_HI_OFF, tid);
    load_tile(Bl, 256, tb + B_LO_OFF, tid);
    CP_COMMIT();

#pragma unroll 1
    for (int c = 0; c < 64; c++) {
        const uint32_t sb = tb + (uint32_t)(c & 1) * STG;
        if (c < 63) {
            const uint32_t nsb = tb + (uint32_t)((c + 1) & 1) * STG;
            const int k1 = (c + 1) * 64;
            load_tile(Ah + k1, 128, nsb + A_HI_OFF, tid);
            load_tile(Al + k1, 128, nsb + A_LO_OFF, tid);
            load_tile(Bh + k1, 256, nsb + B_HI_OFF, tid);
            load_tile(Bl + k1, 256, nsb + B_LO_OFF, tid);
            CP_COMMIT();
            CP_WAIT1();
        } else {
            CP_WAIT0();
        }
        __syncthreads();

#pragma unroll
        for (int ks = 0; ks < 4; ks++) {
            const uint32_t kbc = (uint32_t)(ks * 32);
            uint32_t ah[2][4], al[2][4];
#pragma unroll
            for (int t = 0; t < 2; t++) {
                const uint32_t row = (uint32_t)(wm * 32 + t * 16) + a_row;
                ldsm4(ah[t], sb + A_HI_OFF + swz(row, kbc + a_bc));
                ldsm4(al[t], sb + A_LO_OFF + swz(row, kbc + a_bc));
            }
#pragma unroll
            for (int p = 0; p < 4; p++) {
                const uint32_t row = (uint32_t)(wn * 64 + p * 16) + b_row;
                uint32_t bh[4], bl[4];
                ldsm4(bh, sb + B_HI_OFF + swz(row, kbc + b_bc));
                ldsm4(bl, sb + B_LO_OFF + swz(row, kbc + b_bc));
#pragma unroll
                for (int t = 0; t < 2; t++) {
                    mma16816(d[t][p * 2 + 0], ah[t], bh[0], bh[1]);
                    mma16816(d[t][p * 2 + 1], ah[t], bh[2], bh[3]);
                    mma16816(d[t][p * 2 + 0], al[t], bh[0], bh[1]);
                    mma16816(d[t][p * 2 + 1], al[t], bh[2], bh[3]);
                    mma16816(d[t][p * 2 + 0], ah[t], bl[0], bl[1]);
                    mma16816(d[t][p * 2 + 1], ah[t], bl[2], bl[3]);
                }
            }
        }
        __syncthreads();   // protect stage sb before it is refilled next iter
    }

    // epilogue: d[t][j] -> out rows (mt*128 + wm*32 + t*16 + {g, g+8}),
    //                        cols (nt*256 + wn*64 + j*8 + 2*(lane&3))
    const int r0 = mt * 128 + wm * 32 + (lane >> 2);
    const int c0 = nt * 256 + wn * 64 + (lane & 3) * 2;
#pragma unroll
    for (int t = 0; t < 2; t++) {
#pragma unroll
        for (int j = 0; j < 8; j++) {
            const int col = c0 + j * 8;
            const float b0 = out_b[col], b1 = out_b[col + 1];
            const int row = r0 + t * 16;
            float2 v0 = make_float2(d[t][j][0] + b0, d[t][j][1] + b1);
            float2 v1 = make_float2(d[t][j][2] + b0, d[t][j][3] + b1);
            *reinterpret_cast<float2*>(out + (size_t)row * DDIM + col) = v0;
            *reinterpret_cast<float2*>(out + (size_t)(row + 8) * DDIM + col) = v1;
        }
    }
}

// ------------------------------- launcher --------------------------------------
extern "C" void kernel_launch(void* const* d_in, const int* in_sizes, int n_in,
                              void* d_out, int out_size) {
    const float* hidden      = (const float*)d_in[0];
    const float* slot_w      = (const float*)d_in[1];
    const float* slot_b      = (const float*)d_in[2];
    const float* leaf_logits = (const float*)d_in[3];
    const float* node_params = (const float*)d_in[4];
    const float* out_w       = (const float*)d_in[5];
    const float* out_b       = (const float*)d_in[6];
    float* out = (float*)d_out;

    cudaFuncSetAttribute(gemm_kernel, cudaFuncAttributeMaxDynamicSharedMemorySize, GEMM_SMEM);

    weff_kernel<<<(WDIM * 8 + 255) / 256, 256>>>(leaf_logits);
    split_b_kernel<<<dim3(WDIM / 32, DDIM / 32), dim3(32, 8)>>>(out_w);
    slots_kernel<<<TOK, 256>>>(hidden, slot_w, slot_b);
    roots_kernel<<<dim3(WDIM / 256, TOK / 128), 256>>>(node_params);
    gemm_kernel<<<128, 512, GEMM_SMEM>>>(out, out_b);
}

// round 6
// speedup vs baseline: 1.2327x; 1.2327x over previous
#include <cuda_runtime.h>
#include <cuda_fp16.h>
#include <cstdint>
#include <cstddef>

#define TOK  4096
#define DDIM 1024
#define WDIM 4096

// ------------------------- device scratch (no allocs) -------------------------
__device__ float g_slots[TOK * 8];                  // [tok][slot]
__device__ float g_weff[72 * WDIM];                 // [(l*9+c)][w]
__device__ __half g_ahi[(size_t)TOK * WDIM];        // roots hi  [tok][k=w]
__device__ __half g_alo[(size_t)TOK * WDIM];        // roots lo
__device__ __half g_bhi[(size_t)DDIM * WDIM];       // out_w^T   [n=d][k=w]

// ------------------------------- helpers --------------------------------------
__device__ __forceinline__ float fast_tanh(float x) {
    float e = __expf(2.0f * x);
    return 1.0f - __fdividef(2.0f, e + 1.0f);
}

__device__ __forceinline__ uint32_t smem_u32(const void* p) {
    uint32_t a;
    asm("{ .reg .u64 t; cvta.to.shared.u64 t, %1; cvt.u32.u64 %0, t; }" : "=r"(a) : "l"(p));
    return a;
}

__device__ __forceinline__ uint64_t pack2(float lo, float hi) {
    uint64_t r;
    asm("mov.b64 %0, {%1, %2};" : "=l"(r) : "f"(lo), "f"(hi));
    return r;
}
__device__ __forceinline__ void unpack2(uint64_t v, float& lo, float& hi) {
    asm("mov.b64 {%0, %1}, %2;" : "=f"(lo), "=f"(hi) : "l"(v));
}
__device__ __forceinline__ uint64_t ffma2(uint64_t a, uint64_t b, uint64_t c) {
    uint64_t r;
    asm("fma.rn.f32x2 %0, %1, %2, %3;" : "=l"(r) : "l"(a), "l"(b), "l"(c));
    return r;
}

#define CP16(dst, src) \
    asm volatile("cp.async.cg.shared.global [%0], [%1], 16;" :: "r"(dst), "l"(src) : "memory")
#define CP_COMMIT() asm volatile("cp.async.commit_group;" ::: "memory")
#define CP_WAIT0()  asm volatile("cp.async.wait_group 0;" ::: "memory")
#define CP_WAIT1()  asm volatile("cp.async.wait_group 1;" ::: "memory")

__device__ __forceinline__ void ldsm4(uint32_t (&r)[4], uint32_t addr) {
    asm volatile("ldmatrix.sync.aligned.m8n8.x4.shared.b16 {%0,%1,%2,%3}, [%4];"
                 : "=r"(r[0]), "=r"(r[1]), "=r"(r[2]), "=r"(r[3]) : "r"(addr));
}

__device__ __forceinline__ void mma16816(float (&d)[4], const uint32_t (&a)[4],
                                         uint32_t b0, uint32_t b1) {
    asm volatile("mma.sync.aligned.m16n8k16.row.col.f32.f16.f16.f32 "
                 "{%0,%1,%2,%3}, {%4,%5,%6,%7}, {%8,%9}, {%0,%1,%2,%3};"
                 : "+f"(d[0]), "+f"(d[1]), "+f"(d[2]), "+f"(d[3])
                 : "r"(a[0]), "r"(a[1]), "r"(a[2]), "r"(a[3]), "r"(b0), "r"(b1));
}

// SW128 swizzle for 128B rows (64 fp16 per row)
__device__ __forceinline__ uint32_t swz(uint32_t row, uint32_t bytecol) {
    return row * 128u + (bytecol ^ ((row & 7u) << 4));
}

// -------------------- kernel 1: softmax -> effective leaf weights --------------
__global__ void __launch_bounds__(256) weff_kernel(const float* __restrict__ logits) {
    const int idx = blockIdx.x * 256 + threadIdx.x;   // (w,l)
    if (idx >= WDIM * 8) return;
    const int w = idx >> 3, l = idx & 7;
    const float* p = logits + (size_t)idx * 11;
    float x[11], m = -1e30f;
#pragma unroll
    for (int c = 0; c < 11; c++) { x[c] = p[c]; m = fmaxf(m, x[c]); }
    float s = 0.f;
#pragma unroll
    for (int c = 0; c < 11; c++) { x[c] = __expf(x[c] - m); s += x[c]; }
    const float inv = 1.0f / s;
#pragma unroll
    for (int c = 0; c < 8; c++) g_weff[(l * 9 + c) * WDIM + w] = x[c] * inv;
    g_weff[(l * 9 + 8) * WDIM + w] = (x[10] - x[8]) * inv;   // -1*sel8 + 0*sel9 + 1*sel10
}

// ------------- kernel 2: out_w transpose to fp16  [d][w] -----------------------
__global__ void __launch_bounds__(256) split_b_kernel(const float* __restrict__ ow) {
    __shared__ float tile[32][33];
    const int kt = blockIdx.x * 32, nt = blockIdx.y * 32;
    const int tx = threadIdx.x, ty = threadIdx.y;   // (32,8)
#pragma unroll
    for (int i = 0; i < 32; i += 8)
        tile[ty + i][tx] = ow[(size_t)(kt + ty + i) * DDIM + nt + tx];
    __syncthreads();
#pragma unroll
    for (int i = 0; i < 32; i += 8) {
        const int n = nt + ty + i, k = kt + tx;
        g_bhi[(size_t)n * WDIM + k] = __float2half_rn(tile[tx][ty + i]);
    }
}

// -------------- kernel 3: slots = tanh(hidden @ slot_w + slot_b) ---------------
__global__ void __launch_bounds__(256) slots_kernel(const float* __restrict__ hidden,
                                                    const float* __restrict__ slot_w,
                                                    const float* __restrict__ slot_b) {
    __shared__ float sred[64];
    const int tok = blockIdx.x;
    const int tid = threadIdx.x, lane = tid & 31, warp = tid >> 5;
    float acc[8];
#pragma unroll
    for (int s = 0; s < 8; s++) acc[s] = 0.f;
    const float4* h4 = reinterpret_cast<const float4*>(hidden + (size_t)tok * DDIM);
    for (int i = tid; i < DDIM / 4; i += 256) {
        const float4 h = h4[i];
        const int d = i * 4;
#pragma unroll
        for (int j = 0; j < 4; j++) {
            const float hv = (j == 0) ? h.x : (j == 1) ? h.y : (j == 2) ? h.z : h.w;
            const float4* w4 = reinterpret_cast<const float4*>(slot_w + (size_t)(d + j) * 8);
            const float4 wa = w4[0], wb = w4[1];
            acc[0] = fmaf(hv, wa.x, acc[0]); acc[1] = fmaf(hv, wa.y, acc[1]);
            acc[2] = fmaf(hv, wa.z, acc[2]); acc[3] = fmaf(hv, wa.w, acc[3]);
            acc[4] = fmaf(hv, wb.x, acc[4]); acc[5] = fmaf(hv, wb.y, acc[5]);
            acc[6] = fmaf(hv, wb.z, acc[6]); acc[7] = fmaf(hv, wb.w, acc[7]);
        }
    }
#pragma unroll
    for (int s = 0; s < 8; s++)
#pragma unroll
        for (int o = 16; o > 0; o >>= 1)
            acc[s] += __shfl_xor_sync(0xffffffffu, acc[s], o);
    if (lane == 0) {
#pragma unroll
        for (int s = 0; s < 8; s++) sred[warp * 8 + s] = acc[s];
    }
    __syncthreads();
    if (tid < 8) {
        float v = slot_b[tid];
#pragma unroll
        for (int wp = 0; wp < 8; wp++) v += sred[wp * 8 + tid];
        g_slots[(size_t)tok * 8 + tid] = fast_tanh(v);
    }
}

// ---------------- kernel 4: roots via 3-level tree over 8 leaves ---------------
// grid (WDIM/256, TOK/128), 256 threads; thread owns one w, iterates 128 tokens.
// Leaf dot uses packed fma.rn.f32x2 across leaf pairs (weights pre-packed).
__global__ void __launch_bounds__(256) roots_kernel(const float* __restrict__ np) {
    __shared__ float ssl[128 * 8];
    const int tid = threadIdx.x;
    const int w = blockIdx.x * 256 + tid;
    const int t0 = blockIdx.y * 128;

    // packed weights: wp[p*9+c] = {wt[2p][c], wt[2p+1][c]}, c=8 is bias
    uint64_t wp[36];
#pragma unroll
    for (int p = 0; p < 4; p++)
#pragma unroll
        for (int c = 0; c < 9; c++)
            wp[p * 9 + c] = pack2(g_weff[((2 * p) * 9 + c) * WDIM + w],
                                  g_weff[((2 * p + 1) * 9 + c) * WDIM + w]);

    {
        const float4* src = reinterpret_cast<const float4*>(g_slots + (size_t)t0 * 8);
        reinterpret_cast<float4*>(ssl)[tid] = src[tid];
    }
    // fold: lw*L + rw*R + pw*L*R + dw*(L-R) + nb = (lw+dw)*L + (rw-dw)*R + pw*L*R + nb
    const float lwp = np[0] + np[3], rwm = np[1] - np[3], pw = np[2], nb = np[4];
    __syncthreads();

#pragma unroll 1
    for (int t = 0; t < 128; t++) {
        const float4 sA = *reinterpret_cast<const float4*>(&ssl[t * 8]);
        const float4 sB = *reinterpret_cast<const float4*>(&ssl[t * 8 + 4]);
        uint64_t sp[8];
        sp[0] = pack2(sA.x, sA.x); sp[1] = pack2(sA.y, sA.y);
        sp[2] = pack2(sA.z, sA.z); sp[3] = pack2(sA.w, sA.w);
        sp[4] = pack2(sB.x, sB.x); sp[5] = pack2(sB.y, sB.y);
        sp[6] = pack2(sB.z, sB.z); sp[7] = pack2(sB.w, sB.w);

        uint64_t acc[4];
#pragma unroll
        for (int p = 0; p < 4; p++) acc[p] = wp[p * 9 + 8];
#pragma unroll
        for (int c = 0; c < 8; c++)
#pragma unroll
            for (int p = 0; p < 4; p++)
                acc[p] = ffma2(wp[p * 9 + c], sp[c], acc[p]);

        float v[8];
#pragma unroll
        for (int p = 0; p < 4; p++) unpack2(acc[p], v[2 * p], v[2 * p + 1]);

#pragma unroll
        for (int lvl = 0; lvl < 3; lvl++) {
            const int n = 8 >> (lvl + 1);
#pragma unroll
            for (int i = 0; i < 4; i++) {
                if (i < n) {
                    const float L = v[2 * i], R = v[2 * i + 1];
                    float a = fmaf(lwp, L, nb);
                    a = fmaf(rwm, R, a);
                    a = fmaf(pw * L, R, a);
                    v[i] = fast_tanh(a);
                }
            }
        }
        const float root = v[0];
        const __half hi = __float2half_rn(root);
        const size_t o = (size_t)(t0 + t) * WDIM + w;
        g_ahi[o] = hi;
        g_alo[o] = __float2half_rn(root - __half2float(hi));
    }
}

// ------------------- kernel 5: out = roots @ out_w + out_b ---------------------
// mma.sync fp16 2-split (A = hi+lo exact, B = fp16). CTA tile 128(M)x256(N),
// K-chunk 64, 2-stage cp.async. 512 threads = 16 warps 4x4; warp tile 32x64.
#define STG      65536                      // bytes per stage
#define A_HI_OFF 0                          // 128 x 64 fp16 = 16KB
#define A_LO_OFF 16384
#define B_HI_OFF 32768                      // 256 x 64 fp16 = 32KB
#define GEMM_SMEM (2 * STG + 1024)

__device__ __forceinline__ void load_tile(const __half* __restrict__ g, int rows,
                                          uint32_t sb, int tid) {
    // rows x 64 halves (128B rows), swizzled, 16B granules, 512 threads
    const int n16 = rows * 8;
    for (int e = tid; e < n16; e += 512) {
        const int r = e >> 3, c = e & 7;
        CP16(sb + swz((uint32_t)r, (uint32_t)(c * 16)), g + (size_t)r * WDIM + c * 8);
    }
}

__global__ void __launch_bounds__(512, 1) gemm_kernel(float* __restrict__ out,
                                                      const float* __restrict__ out_b) {
    extern __shared__ char dsm[];
    const uint32_t tb = (smem_u32(dsm) + 1023u) & ~1023u;

    const int tid = threadIdx.x, lane = tid & 31, wid = tid >> 5;
    const int mt = blockIdx.x & 31, nt = blockIdx.x >> 5;
    const int wm = wid & 3, wn = wid >> 2;         // 4x4 warp grid

    const __half* Ah = g_ahi + (size_t)(mt * 128) * WDIM;
    const __half* Al = g_alo + (size_t)(mt * 128) * WDIM;
    const __half* Bh = g_bhi + (size_t)(nt * 256) * WDIM;

    float d[2][8][4];
#pragma unroll
    for (int t = 0; t < 2; t++)
#pragma unroll
        for (int j = 0; j < 8; j++)
#pragma unroll
            for (int q = 0; q < 4; q++) d[t][j][q] = 0.f;

    // ldmatrix lane addressing (within a 16x16 b16 tile, 128B rows)
    const uint32_t a_row = (uint32_t)(lane & 15);
    const uint32_t a_bc  = (uint32_t)((lane >> 4) * 16);
    const uint32_t b_row = (uint32_t)(((lane >> 4) << 3) + (lane & 7));
    const uint32_t b_bc  = (uint32_t)(((lane >> 3) & 1) * 16);

    // prologue
    load_tile(Ah, 128, tb + A_HI_OFF, tid);
    load_tile(Al, 128, tb + A_LO_OFF, tid);
    load_tile(Bh, 256, tb + B_HI_OFF, tid);
    CP_COMMIT();

#pragma unroll 1
    for (int c = 0; c < 64; c++) {
        const uint32_t sb = tb + (uint32_t)(c & 1) * STG;
        if (c < 63) {
            const uint32_t nsb = tb + (uint32_t)((c + 1) & 1) * STG;
            const int k1 = (c + 1) * 64;
            load_tile(Ah + k1, 128, nsb + A_HI_OFF, tid);
            load_tile(Al + k1, 128, nsb + A_LO_OFF, tid);
            load_tile(Bh + k1, 256, nsb + B_HI_OFF, tid);
            CP_COMMIT();
            CP_WAIT1();
        } else {
            CP_WAIT0();
        }
        __syncthreads();

#pragma unroll
        for (int ks = 0; ks < 4; ks++) {
            const uint32_t kbc = (uint32_t)(ks * 32);
            uint32_t ah[2][4], al[2][4];
#pragma unroll
            for (int t = 0; t < 2; t++) {
                const uint32_t row = (uint32_t)(wm * 32 + t * 16) + a_row;
                ldsm4(ah[t], sb + A_HI_OFF + swz(row, kbc + a_bc));
                ldsm4(al[t], sb + A_LO_OFF + swz(row, kbc + a_bc));
            }
#pragma unroll
            for (int p = 0; p < 4; p++) {
                const uint32_t row = (uint32_t)(wn * 64 + p * 16) + b_row;
                uint32_t bh[4];
                ldsm4(bh, sb + B_HI_OFF + swz(row, kbc + b_bc));
#pragma unroll
                for (int t = 0; t < 2; t++) {
                    mma16816(d[t][p * 2 + 0], ah[t], bh[0], bh[1]);
                    mma16816(d[t][p * 2 + 1], ah[t], bh[2], bh[3]);
                    mma16816(d[t][p * 2 + 0], al[t], bh[0], bh[1]);
                    mma16816(d[t][p * 2 + 1], al[t], bh[2], bh[3]);
                }
            }
        }
        __syncthreads();   // protect stage sb before it is refilled next iter
    }

    // epilogue
    const int r0 = mt * 128 + wm * 32 + (lane >> 2);
    const int c0 = nt * 256 + wn * 64 + (lane & 3) * 2;
#pragma unroll
    for (int t = 0; t < 2; t++) {
#pragma unroll
        for (int j = 0; j < 8; j++) {
            const int col = c0 + j * 8;
            const float b0 = out_b[col], b1 = out_b[col + 1];
            const int row = r0 + t * 16;
            float2 v0 = make_float2(d[t][j][0] + b0, d[t][j][1] + b1);
            float2 v1 = make_float2(d[t][j][2] + b0, d[t][j][3] + b1);
            *reinterpret_cast<float2*>(out + (size_t)row * DDIM + col) = v0;
            *reinterpret_cast<float2*>(out + (size_t)(row + 8) * DDIM + col) = v1;
        }
    }
}

// ------------------------------- launcher --------------------------------------
extern "C" void kernel_launch(void* const* d_in, const int* in_sizes, int n_in,
                              void* d_out, int out_size) {
    const float* hidden      = (const float*)d_in[0];
    const float* slot_w      = (const float*)d_in[1];
    const float* slot_b      = (const float*)d_in[2];
    const float* leaf_logits = (const float*)d_in[3];
    const float* node_params = (const float*)d_in[4];
    const float* out_w       = (const float*)d_in[5];
    const float* out_b       = (const float*)d_in[6];
    float* out = (float*)d_out;

    cudaFuncSetAttribute(gemm_kernel, cudaFuncAttributeMaxDynamicSharedMemorySize, GEMM_SMEM);

    weff_kernel<<<(WDIM * 8 + 255) / 256, 256>>>(leaf_logits);
    split_b_kernel<<<dim3(WDIM / 32, DDIM / 32), dim3(32, 8)>>>(out_w);
    slots_kernel<<<TOK, 256>>>(hidden, slot_w, slot_b);
    roots_kernel<<<dim3(WDIM / 256, TOK / 128), 256>>>(node_params);
    gemm_kernel<<<128, 512, GEMM_SMEM>>>(out, out_b);
}

// round 7
// speedup vs baseline: 1.6675x; 1.3527x over previous
#include <cuda_runtime.h>
#include <cuda_fp16.h>
#include <cstdint>
#include <cstddef>

#define TOK  4096
#define DDIM 1024
#define WDIM 4096

// ------------------------- device scratch (no allocs) -------------------------
__device__ float g_slots[TOK * 8];                  // [tok][slot]
__device__ float g_weff[72 * WDIM];                 // [(l*9+c)][w]
__device__ __half g_ahi[(size_t)TOK * WDIM];        // roots fp16 [tok][k=w]
__device__ __half g_bhi[(size_t)DDIM * WDIM];       // out_w^T fp16 [n=d][k=w]

// ------------------------------- helpers --------------------------------------
__device__ __forceinline__ float fast_tanh(float x) {
    float e = __expf(2.0f * x);
    return 1.0f - __fdividef(2.0f, e + 1.0f);
}

__device__ __forceinline__ uint32_t smem_u32(const void* p) {
    uint32_t a;
    asm("{ .reg .u64 t; cvta.to.shared.u64 t, %1; cvt.u32.u64 %0, t; }" : "=r"(a) : "l"(p));
    return a;
}

__device__ __forceinline__ uint64_t pack2(float lo, float hi) {
    uint64_t r;
    asm("mov.b64 %0, {%1, %2};" : "=l"(r) : "f"(lo), "f"(hi));
    return r;
}
__device__ __forceinline__ void unpack2(uint64_t v, float& lo, float& hi) {
    asm("mov.b64 {%0, %1}, %2;" : "=f"(lo), "=f"(hi) : "l"(v));
}
__device__ __forceinline__ uint64_t ffma2(uint64_t a, uint64_t b, uint64_t c) {
    uint64_t r;
    asm("fma.rn.f32x2 %0, %1, %2, %3;" : "=l"(r) : "l"(a), "l"(b), "l"(c));
    return r;
}

#define CP16(dst, src) \
    asm volatile("cp.async.cg.shared.global [%0], [%1], 16;" :: "r"(dst), "l"(src) : "memory")
#define CP_COMMIT() asm volatile("cp.async.commit_group;" ::: "memory")
#define CP_WAIT0()  asm volatile("cp.async.wait_group 0;" ::: "memory")
#define CP_WAIT1()  asm volatile("cp.async.wait_group 1;" ::: "memory")

__device__ __forceinline__ void ldsm4(uint32_t (&r)[4], uint32_t addr) {
    asm volatile("ldmatrix.sync.aligned.m8n8.x4.shared.b16 {%0,%1,%2,%3}, [%4];"
                 : "=r"(r[0]), "=r"(r[1]), "=r"(r[2]), "=r"(r[3]) : "r"(addr));
}

__device__ __forceinline__ void mma16816(float (&d)[4], const uint32_t (&a)[4],
                                         uint32_t b0, uint32_t b1) {
    asm volatile("mma.sync.aligned.m16n8k16.row.col.f32.f16.f16.f32 "
                 "{%0,%1,%2,%3}, {%4,%5,%6,%7}, {%8,%9}, {%0,%1,%2,%3};"
                 : "+f"(d[0]), "+f"(d[1]), "+f"(d[2]), "+f"(d[3])
                 : "r"(a[0]), "r"(a[1]), "r"(a[2]), "r"(a[3]), "r"(b0), "r"(b1));
}

// SW128 swizzle for 128B rows (64 fp16 per row)
__device__ __forceinline__ uint32_t swz(uint32_t row, uint32_t bytecol) {
    return row * 128u + (bytecol ^ ((row & 7u) << 4));
}

// -------------------- kernel 1: softmax -> effective leaf weights --------------
__global__ void __launch_bounds__(256) weff_kernel(const float* __restrict__ logits) {
    const int idx = blockIdx.x * 256 + threadIdx.x;   // (w,l)
    if (idx >= WDIM * 8) return;
    const int w = idx >> 3, l = idx & 7;
    const float* p = logits + (size_t)idx * 11;
    float x[11], m = -1e30f;
#pragma unroll
    for (int c = 0; c < 11; c++) { x[c] = p[c]; m = fmaxf(m, x[c]); }
    float s = 0.f;
#pragma unroll
    for (int c = 0; c < 11; c++) { x[c] = __expf(x[c] - m); s += x[c]; }
    const float inv = 1.0f / s;
#pragma unroll
    for (int c = 0; c < 8; c++) g_weff[(l * 9 + c) * WDIM + w] = x[c] * inv;
    g_weff[(l * 9 + 8) * WDIM + w] = (x[10] - x[8]) * inv;   // -1*sel8 + 0*sel9 + 1*sel10
}

// ------------- kernel 2: out_w transpose to fp16  [d][w] -----------------------
__global__ void __launch_bounds__(256) split_b_kernel(const float* __restrict__ ow) {
    __shared__ float tile[32][33];
    const int kt = blockIdx.x * 32, nt = blockIdx.y * 32;
    const int tx = threadIdx.x, ty = threadIdx.y;   // (32,8)
#pragma unroll
    for (int i = 0; i < 32; i += 8)
        tile[ty + i][tx] = ow[(size_t)(kt + ty + i) * DDIM + nt + tx];
    __syncthreads();
#pragma unroll
    for (int i = 0; i < 32; i += 8) {
        const int n = nt + ty + i, k = kt + tx;
        g_bhi[(size_t)n * WDIM + k] = __float2half_rn(tile[tx][ty + i]);
    }
}

// -------------- kernel 3: slots = tanh(hidden @ slot_w + slot_b) ---------------
__global__ void __launch_bounds__(256) slots_kernel(const float* __restrict__ hidden,
                                                    const float* __restrict__ slot_w,
                                                    const float* __restrict__ slot_b) {
    __shared__ float sred[64];
    const int tok = blockIdx.x;
    const int tid = threadIdx.x, lane = tid & 31, warp = tid >> 5;
    float acc[8];
#pragma unroll
    for (int s = 0; s < 8; s++) acc[s] = 0.f;
    const float4* h4 = reinterpret_cast<const float4*>(hidden + (size_t)tok * DDIM);
    for (int i = tid; i < DDIM / 4; i += 256) {
        const float4 h = h4[i];
        const int d = i * 4;
#pragma unroll
        for (int j = 0; j < 4; j++) {
            const float hv = (j == 0) ? h.x : (j == 1) ? h.y : (j == 2) ? h.z : h.w;
            const float4* w4 = reinterpret_cast<const float4*>(slot_w + (size_t)(d + j) * 8);
            const float4 wa = w4[0], wb = w4[1];
            acc[0] = fmaf(hv, wa.x, acc[0]); acc[1] = fmaf(hv, wa.y, acc[1]);
            acc[2] = fmaf(hv, wa.z, acc[2]); acc[3] = fmaf(hv, wa.w, acc[3]);
            acc[4] = fmaf(hv, wb.x, acc[4]); acc[5] = fmaf(hv, wb.y, acc[5]);
            acc[6] = fmaf(hv, wb.z, acc[6]); acc[7] = fmaf(hv, wb.w, acc[7]);
        }
    }
#pragma unroll
    for (int s = 0; s < 8; s++)
#pragma unroll
        for (int o = 16; o > 0; o >>= 1)
            acc[s] += __shfl_xor_sync(0xffffffffu, acc[s], o);
    if (lane == 0) {
#pragma unroll
        for (int s = 0; s < 8; s++) sred[warp * 8 + s] = acc[s];
    }
    __syncthreads();
    if (tid < 8) {
        float v = slot_b[tid];
#pragma unroll
        for (int wp = 0; wp < 8; wp++) v += sred[wp * 8 + tid];
        g_slots[(size_t)tok * 8 + tid] = fast_tanh(v);
    }
}

// ---------------- kernel 4: roots via 3-level tree over 8 leaves ---------------
// grid (WDIM/256, TOK/128), 256 threads; thread owns one w, 2 tokens per iter
// for ILP (the 3-level tanh chain is latency-exposed at occ=2 CTA/SM).
__global__ void __launch_bounds__(256) roots_kernel(const float* __restrict__ np) {
    __shared__ float ssl[128 * 8];
    const int tid = threadIdx.x;
    const int w = blockIdx.x * 256 + tid;
    const int t0 = blockIdx.y * 128;

    // packed weights: wp[p*9+c] = {wt[2p][c], wt[2p+1][c]}, c=8 is bias
    uint64_t wp[36];
#pragma unroll
    for (int p = 0; p < 4; p++)
#pragma unroll
        for (int c = 0; c < 9; c++)
            wp[p * 9 + c] = pack2(g_weff[((2 * p) * 9 + c) * WDIM + w],
                                  g_weff[((2 * p + 1) * 9 + c) * WDIM + w]);

    {
        const float4* src = reinterpret_cast<const float4*>(g_slots + (size_t)t0 * 8);
        reinterpret_cast<float4*>(ssl)[tid] = src[tid];
    }
    // fold: lw*L + rw*R + pw*L*R + dw*(L-R) + nb = (lw+dw)*L + (rw-dw)*R + pw*L*R + nb
    const float lwp = np[0] + np[3], rwm = np[1] - np[3], pw = np[2], nb = np[4];
    __syncthreads();

#pragma unroll 1
    for (int t = 0; t < 128; t += 2) {
        float v[2][8];
#pragma unroll
        for (int u = 0; u < 2; u++) {
            const float4 sA = *reinterpret_cast<const float4*>(&ssl[(t + u) * 8]);
            const float4 sB = *reinterpret_cast<const float4*>(&ssl[(t + u) * 8 + 4]);
            uint64_t sp[8];
            sp[0] = pack2(sA.x, sA.x); sp[1] = pack2(sA.y, sA.y);
            sp[2] = pack2(sA.z, sA.z); sp[3] = pack2(sA.w, sA.w);
            sp[4] = pack2(sB.x, sB.x); sp[5] = pack2(sB.y, sB.y);
            sp[6] = pack2(sB.z, sB.z); sp[7] = pack2(sB.w, sB.w);

            uint64_t acc[4];
#pragma unroll
            for (int p = 0; p < 4; p++) acc[p] = wp[p * 9 + 8];
#pragma unroll
            for (int c = 0; c < 8; c++)
#pragma unroll
                for (int p = 0; p < 4; p++)
                    acc[p] = ffma2(wp[p * 9 + c], sp[c], acc[p]);
#pragma unroll
            for (int p = 0; p < 4; p++) unpack2(acc[p], v[u][2 * p], v[u][2 * p + 1]);
        }

        // interleave the two tokens' tree reductions (independent chains)
#pragma unroll
        for (int lvl = 0; lvl < 3; lvl++) {
            const int n = 8 >> (lvl + 1);
#pragma unroll
            for (int i = 0; i < 4; i++) {
                if (i < n) {
#pragma unroll
                    for (int u = 0; u < 2; u++) {
                        const float L = v[u][2 * i], R = v[u][2 * i + 1];
                        float a = fmaf(lwp, L, nb);
                        a = fmaf(rwm, R, a);
                        a = fmaf(pw * L, R, a);
                        v[u][i] = fast_tanh(a);
                    }
                }
            }
        }
#pragma unroll
        for (int u = 0; u < 2; u++)
            g_ahi[(size_t)(t0 + t + u) * WDIM + w] = __float2half_rn(v[u][0]);
    }
}

// ------------------- kernel 5: out = roots @ out_w + out_b ---------------------
// mma.sync fp16 single-term. CTA tile 128(M)x256(N), K-chunk 64, 2-stage
// cp.async. 512 threads = 16 warps 4x4; warp tile 32x64.
#define STG      49152                      // bytes per stage (A 16K + B 32K)
#define A_OFF    0                          // 128 x 64 fp16
#define B_OFF    16384                      // 256 x 64 fp16
#define GEMM_SMEM (2 * STG + 1024)

__device__ __forceinline__ void load_tile(const __half* __restrict__ g, int rows,
                                          uint32_t sb, int tid) {
    // rows x 64 halves (128B rows), swizzled, 16B granules, 512 threads
    const int n16 = rows * 8;
    for (int e = tid; e < n16; e += 512) {
        const int r = e >> 3, c = e & 7;
        CP16(sb + swz((uint32_t)r, (uint32_t)(c * 16)), g + (size_t)r * WDIM + c * 8);
    }
}

__global__ void __launch_bounds__(512, 1) gemm_kernel(float* __restrict__ out,
                                                      const float* __restrict__ out_b) {
    extern __shared__ char dsm[];
    const uint32_t tb = (smem_u32(dsm) + 1023u) & ~1023u;

    const int tid = threadIdx.x, lane = tid & 31, wid = tid >> 5;
    const int mt = blockIdx.x & 31, nt = blockIdx.x >> 5;
    const int wm = wid & 3, wn = wid >> 2;         // 4x4 warp grid

    const __half* Ah = g_ahi + (size_t)(mt * 128) * WDIM;
    const __half* Bh = g_bhi + (size_t)(nt * 256) * WDIM;

    float d[2][8][4];
#pragma unroll
    for (int t = 0; t < 2; t++)
#pragma unroll
        for (int j = 0; j < 8; j++)
#pragma unroll
            for (int q = 0; q < 4; q++) d[t][j][q] = 0.f;

    // ldmatrix lane addressing (within a 16x16 b16 tile, 128B rows)
    const uint32_t a_row = (uint32_t)(lane & 15);
    const uint32_t a_bc  = (uint32_t)((lane >> 4) * 16);
    const uint32_t b_row = (uint32_t)(((lane >> 4) << 3) + (lane & 7));
    const uint32_t b_bc  = (uint32_t)(((lane >> 3) & 1) * 16);

    // prologue
    load_tile(Ah, 128, tb + A_OFF, tid);
    load_tile(Bh, 256, tb + B_OFF, tid);
    CP_COMMIT();

#pragma unroll 1
    for (int c = 0; c < 64; c++) {
        const uint32_t sb = tb + (uint32_t)(c & 1) * STG;
        if (c < 63) {
            const uint32_t nsb = tb + (uint32_t)((c + 1) & 1) * STG;
            const int k1 = (c + 1) * 64;
            load_tile(Ah + k1, 128, nsb + A_OFF, tid);
            load_tile(Bh + k1, 256, nsb + B_OFF, tid);
            CP_COMMIT();
            CP_WAIT1();
        } else {
            CP_WAIT0();
        }
        __syncthreads();

#pragma unroll
        for (int ks = 0; ks < 4; ks++) {
            const uint32_t kbc = (uint32_t)(ks * 32);
            uint32_t ah[2][4];
#pragma unroll
            for (int t = 0; t < 2; t++) {
                const uint32_t row = (uint32_t)(wm * 32 + t * 16) + a_row;
                ldsm4(ah[t], sb + A_OFF + swz(row, kbc + a_bc));
            }
#pragma unroll
            for (int p = 0; p < 4; p++) {
                const uint32_t row = (uint32_t)(wn * 64 + p * 16) + b_row;
                uint32_t bh[4];
                ldsm4(bh, sb + B_OFF + swz(row, kbc + b_bc));
#pragma unroll
                for (int t = 0; t < 2; t++) {
                    mma16816(d[t][p * 2 + 0], ah[t], bh[0], bh[1]);
                    mma16816(d[t][p * 2 + 1], ah[t], bh[2], bh[3]);
                }
            }
        }
        __syncthreads();   // protect stage sb before it is refilled next iter
    }

    // epilogue
    const int r0 = mt * 128 + wm * 32 + (lane >> 2);
    const int c0 = nt * 256 + wn * 64 + (lane & 3) * 2;
#pragma unroll
    for (int t = 0; t < 2; t++) {
#pragma unroll
        for (int j = 0; j < 8; j++) {
            const int col = c0 + j * 8;
            const float b0 = out_b[col], b1 = out_b[col + 1];
            const int row = r0 + t * 16;
            float2 v0 = make_float2(d[t][j][0] + b0, d[t][j][1] + b1);
            float2 v1 = make_float2(d[t][j][2] + b0, d[t][j][3] + b1);
            *reinterpret_cast<float2*>(out + (size_t)row * DDIM + col) = v0;
            *reinterpret_cast<float2*>(out + (size_t)(row + 8) * DDIM + col) = v1;
        }
    }
}

// ------------------------------- launcher --------------------------------------
extern "C" void kernel_launch(void* const* d_in, const int* in_sizes, int n_in,
                              void* d_out, int out_size) {
    const float* hidden      = (const float*)d_in[0];
    const float* slot_w      = (const float*)d_in[1];
    const float* slot_b      = (const float*)d_in[2];
    const float* leaf_logits = (const float*)d_in[3];
    const float* node_params = (const float*)d_in[4];
    const float* out_w       = (const float*)d_in[5];
    const float* out_b       = (const float*)d_in[6];
    float* out = (float*)d_out;

    cudaFuncSetAttribute(gemm_kernel, cudaFuncAttributeMaxDynamicSharedMemorySize, GEMM_SMEM);

    weff_kernel<<<(WDIM * 8 + 255) / 256, 256>>>(leaf_logits);
    split_b_kernel<<<dim3(WDIM / 32, DDIM / 32), dim3(32, 8)>>>(out_w);
    slots_kernel<<<TOK, 256>>>(hidden, slot_w, slot_b);
    roots_kernel<<<dim3(WDIM / 256, TOK / 128), 256>>>(node_params);
    gemm_kernel<<<128, 512, GEMM_SMEM>>>(out, out_b);
}